// round 2
// baseline (speedup 1.0000x reference)
#include <cuda_runtime.h>
#include <math.h>

// Problem constants
#define BB 32
#define VV 50
#define DD 6
#define HH 256
#define TT 3            // edge types used (skip_first)
#define EE 2450         // V*(V-1)
#define NBV 1600        // B*V

// Scratch (device globals — allocation-free)
__device__ float g_P[(size_t)NBV * TT * 2 * HH];      // [row][t][dir][h], dir0=recv(+b1), dir1=send
__device__ float g_msg[(size_t)BB * EE * HH];         // per-edge messages summed over types (ew applied)
__device__ float g_agg[(size_t)NBV * HH];             // aggregated per node

// ---------------------------------------------------------------------------
// K1: node projections.  C[1600, 1536] = hidden[1600,256] @ W1-slices^T
// grid (25, 6): blockIdx.y -> (t, dir).  64 rows x 256 cols per block.
// ---------------------------------------------------------------------------
__global__ void __launch_bounds__(256, 1)
k1_proj(const float* __restrict__ hidden, const float* __restrict__ W1,
        const float* __restrict__ b1) {
    extern __shared__ float sm[];
    float (*sAT)[65] = (float(*)[65])sm;                   // [256][65] A transposed
    float (*sW)[256] = (float(*)[256])(sm + 256 * 65);     // [16][256]

    const int tid = threadIdx.x;
    const int tx = tid & 15, ty = tid >> 4;
    const int row0 = blockIdx.x * 64;
    const int nt = blockIdx.y;
    const int t = nt >> 1, dir = nt & 1;

    for (int i = tid; i < 64 * 256; i += 256) {
        int k = i & 255, r = i >> 8;
        sAT[k][r] = hidden[(size_t)(row0 + r) * 256 + k];
    }
    __syncthreads();

    float acc[4][16];
#pragma unroll
    for (int r = 0; r < 4; r++)
#pragma unroll
        for (int c = 0; c < 16; c++) acc[r][c] = 0.f;

    const float* wbase = W1 + ((size_t)t * 256 + tid) * 512 + dir * 256;

    for (int kc = 0; kc < 256; kc += 16) {
        const float4* wp = reinterpret_cast<const float4*>(wbase + kc);
        float4 q0 = wp[0], q1 = wp[1], q2 = wp[2], q3 = wp[3];
        sW[0][tid] = q0.x; sW[1][tid] = q0.y; sW[2][tid] = q0.z; sW[3][tid] = q0.w;
        sW[4][tid] = q1.x; sW[5][tid] = q1.y; sW[6][tid] = q1.z; sW[7][tid] = q1.w;
        sW[8][tid] = q2.x; sW[9][tid] = q2.y; sW[10][tid] = q2.z; sW[11][tid] = q2.w;
        sW[12][tid] = q3.x; sW[13][tid] = q3.y; sW[14][tid] = q3.z; sW[15][tid] = q3.w;
        __syncthreads();
#pragma unroll
        for (int kk = 0; kk < 16; ++kk) {
            float a0 = sAT[kc + kk][ty * 4 + 0];
            float a1 = sAT[kc + kk][ty * 4 + 1];
            float a2 = sAT[kc + kk][ty * 4 + 2];
            float a3 = sAT[kc + kk][ty * 4 + 3];
#pragma unroll
            for (int c = 0; c < 16; c++) {
                float w = sW[kk][c * 16 + tx];
                acc[0][c] += a0 * w; acc[1][c] += a1 * w;
                acc[2][c] += a2 * w; acc[3][c] += a3 * w;
            }
        }
        __syncthreads();
    }

#pragma unroll
    for (int r = 0; r < 4; r++) {
        int row = row0 + ty * 4 + r;
        float* outp = g_P + (((size_t)row * TT + t) * 2 + dir) * 256;
#pragma unroll
        for (int c = 0; c < 16; c++) {
            int col = c * 16 + tx;
            float v = acc[r][c];
            if (dir == 0) v += b1[t * 256 + col];
            outp[col] = v;
        }
    }
}

// ---------------------------------------------------------------------------
// K2: per-edge layer1(tanh) + layer2 GEMM + tanh + edge-weight, summed over t.
// grid (39, 32): 64-edge tile x batch.  Writes g_msg[b][e][h].
// ---------------------------------------------------------------------------
__global__ void __launch_bounds__(256, 1)
k2_msg(const float* __restrict__ edges, const float* __restrict__ W2,
       const float* __restrict__ b2) {
    extern __shared__ float sm[];
    float (*sAT)[65] = (float(*)[65])sm;                   // h1 transposed [256][65]
    float (*sW)[256] = (float(*)[256])(sm + 256 * 65);
    float* sEw = sm + 256 * 65 + 16 * 256;                 // [3][64]
    float* sB2 = sEw + 192;                                // [768]

    const int tid = threadIdx.x;
    const int tx = tid & 15, ty = tid >> 4;
    const int b = blockIdx.y;
    const int e0 = blockIdx.x * 64;

    for (int i = tid; i < 192; i += 256) {
        int t = i / 64, el = i - t * 64;
        int e = e0 + el;
        sEw[i] = (e < EE) ? edges[((size_t)b * EE + e) * 4 + 1 + t] : 0.f;
    }
    for (int i = tid; i < 768; i += 256) sB2[i] = b2[i];
    __syncthreads();

    float msgacc[4][16];
#pragma unroll
    for (int r = 0; r < 4; r++)
#pragma unroll
        for (int c = 0; c < 16; c++) msgacc[r][c] = 0.f;

    for (int t = 0; t < TT; t++) {
        // build h1 tile (transposed)
        for (int i = tid; i < 64 * 256; i += 256) {
            int h = i & 255, el = i >> 8;
            int e = e0 + el;
            float v = 0.f;
            if (e < EE) {
                int s = e / 49;
                int j = e - s * 49;
                int vr = j + (j >= s);
                const float* pr = g_P + (((size_t)(b * VV + vr) * TT + t) * 2 + 0) * 256;
                const float* ps = g_P + (((size_t)(b * VV + s) * TT + t) * 2 + 1) * 256;
                v = tanhf(pr[h] + ps[h]);
            }
            sAT[h][el] = v;
        }
        __syncthreads();

        float acc[4][16];
#pragma unroll
        for (int r = 0; r < 4; r++)
#pragma unroll
            for (int c = 0; c < 16; c++) acc[r][c] = 0.f;

        const float* wbase = W2 + ((size_t)t * 256 + tid) * 256;
        for (int kc = 0; kc < 256; kc += 16) {
            const float4* wp = reinterpret_cast<const float4*>(wbase + kc);
            float4 q0 = wp[0], q1 = wp[1], q2 = wp[2], q3 = wp[3];
            sW[0][tid] = q0.x; sW[1][tid] = q0.y; sW[2][tid] = q0.z; sW[3][tid] = q0.w;
            sW[4][tid] = q1.x; sW[5][tid] = q1.y; sW[6][tid] = q1.z; sW[7][tid] = q1.w;
            sW[8][tid] = q2.x; sW[9][tid] = q2.y; sW[10][tid] = q2.z; sW[11][tid] = q2.w;
            sW[12][tid] = q3.x; sW[13][tid] = q3.y; sW[14][tid] = q3.z; sW[15][tid] = q3.w;
            __syncthreads();
#pragma unroll
            for (int kk = 0; kk < 16; ++kk) {
                float a0 = sAT[kc + kk][ty * 4 + 0];
                float a1 = sAT[kc + kk][ty * 4 + 1];
                float a2 = sAT[kc + kk][ty * 4 + 2];
                float a3 = sAT[kc + kk][ty * 4 + 3];
#pragma unroll
                for (int c = 0; c < 16; c++) {
                    float w = sW[kk][c * 16 + tx];
                    acc[0][c] += a0 * w; acc[1][c] += a1 * w;
                    acc[2][c] += a2 * w; acc[3][c] += a3 * w;
                }
            }
            __syncthreads();
        }

#pragma unroll
        for (int r = 0; r < 4; r++) {
            float ew = sEw[t * 64 + ty * 4 + r];
#pragma unroll
            for (int c = 0; c < 16; c++) {
                int col = c * 16 + tx;
                msgacc[r][c] += tanhf(acc[r][c] + sB2[t * 256 + col]) * ew;
            }
        }
        __syncthreads();   // before rebuilding sAT for next t
    }

#pragma unroll
    for (int r = 0; r < 4; r++) {
        int e = e0 + ty * 4 + r;
        if (e < EE) {
            float* o = g_msg + ((size_t)b * EE + e) * 256;
#pragma unroll
            for (int c = 0; c < 16; c++) o[c * 16 + tx] = msgacc[r][c];
        }
    }
}

// ---------------------------------------------------------------------------
// K3: aggregate incoming edges per node.  grid 1600, 256 threads.
// ---------------------------------------------------------------------------
__global__ void k3_agg() {
    const int bv = blockIdx.x;
    const int b = bv / VV, v = bv - b * VV;
    const int h = threadIdx.x;
    const float* base = g_msg + (size_t)b * EE * 256;
    float s = 0.f;
    for (int snd = 0; snd < VV; ++snd) {
        if (snd == v) continue;
        int j = (v < snd) ? v : v - 1;
        s += base[(size_t)(snd * 49 + j) * 256 + h];
    }
    g_agg[(size_t)bv * 256 + h] = s * (1.f / 147.f);   // /norm(3) /(V-1)(49)
}

// ---------------------------------------------------------------------------
// K4: fused GRU update + output MLP. 32-row tiles, 5 smem GEMMs.
// ---------------------------------------------------------------------------
__device__ __forceinline__ void gemm32(const float* __restrict__ W,
                                       const float (*sAT)[33],
                                       float (*sW)[256],
                                       float acc[2][16], int tx, int ty) {
#pragma unroll
    for (int r = 0; r < 2; r++)
#pragma unroll
        for (int c = 0; c < 16; c++) acc[r][c] = 0.f;
    const float* wbase = W + (size_t)threadIdx.x * 256;
    for (int kc = 0; kc < 256; kc += 16) {
        const float4* wp = reinterpret_cast<const float4*>(wbase + kc);
        float4 q0 = wp[0], q1 = wp[1], q2 = wp[2], q3 = wp[3];
        sW[0][threadIdx.x] = q0.x; sW[1][threadIdx.x] = q0.y;
        sW[2][threadIdx.x] = q0.z; sW[3][threadIdx.x] = q0.w;
        sW[4][threadIdx.x] = q1.x; sW[5][threadIdx.x] = q1.y;
        sW[6][threadIdx.x] = q1.z; sW[7][threadIdx.x] = q1.w;
        sW[8][threadIdx.x] = q2.x; sW[9][threadIdx.x] = q2.y;
        sW[10][threadIdx.x] = q2.z; sW[11][threadIdx.x] = q2.w;
        sW[12][threadIdx.x] = q3.x; sW[13][threadIdx.x] = q3.y;
        sW[14][threadIdx.x] = q3.z; sW[15][threadIdx.x] = q3.w;
        __syncthreads();
#pragma unroll
        for (int kk = 0; kk < 16; ++kk) {
            float a0 = sAT[kc + kk][ty * 2 + 0];
            float a1 = sAT[kc + kk][ty * 2 + 1];
#pragma unroll
            for (int c = 0; c < 16; c++) {
                float w = sW[kk][c * 16 + tx];
                acc[0][c] += a0 * w;
                acc[1][c] += a1 * w;
            }
        }
        __syncthreads();
    }
}

__global__ void __launch_bounds__(256, 1)
k4_gru(const float* __restrict__ inputs, const float* __restrict__ hidden,
       const float* __restrict__ Whr, const float* __restrict__ Whi,
       const float* __restrict__ Whh,
       const float* __restrict__ Wir, const float* __restrict__ bir,
       const float* __restrict__ Wii, const float* __restrict__ bii,
       const float* __restrict__ Win, const float* __restrict__ binw,
       const float* __restrict__ Wo1, const float* __restrict__ bo1,
       const float* __restrict__ Wo2, const float* __restrict__ bo2,
       const float* __restrict__ Wo3, const float* __restrict__ bo3,
       float* __restrict__ out) {
    extern __shared__ float sm[];
    float (*sA)[33] = (float(*)[33])sm;                       // [256][33]
    float (*sB)[33] = (float(*)[33])(sm + 256 * 33);          // [256][33]
    float (*sW)[256] = (float(*)[256])(sm + 2 * 256 * 33);    // [16][256]
    float* sX = sm + 2 * 256 * 33 + 16 * 256;                 // [32*6]

    const int tid = threadIdx.x;
    const int tx = tid & 15, ty = tid >> 4;
    const int row0 = blockIdx.x * 32;

    for (int i = tid; i < 32 * 256; i += 256) {
        int k = i & 255, r = i >> 8;
        sA[k][r] = g_agg[(size_t)(row0 + r) * 256 + k];
    }
    if (tid < 192) sX[tid] = inputs[(size_t)row0 * 6 + tid];
    __syncthreads();

    float accR[2][16], accI[2][16], accN[2][16];
    gemm32(Whr, sA, sW, accR, tx, ty);
    gemm32(Whi, sA, sW, accI, tx, ty);
    gemm32(Whh, sA, sW, accN, tx, ty);

    float hn[2][16];
#pragma unroll
    for (int r = 0; r < 2; r++) {
        int row = ty * 2 + r;
        int grow = row0 + row;
#pragma unroll
        for (int c = 0; c < 16; c++) {
            int col = c * 16 + tx;
            float xr = bir[col], xi = bii[col], xn = binw[col];
#pragma unroll
            for (int d = 0; d < 6; d++) {
                float xd = sX[row * 6 + d];
                xr += Wir[col * 6 + d] * xd;
                xi += Wii[col * 6 + d] * xd;
                xn += Win[col * 6 + d] * xd;
            }
            float rg = 1.f / (1.f + expf(-(accR[r][c] + xr)));
            float ig = 1.f / (1.f + expf(-(accI[r][c] + xi)));
            float ng = tanhf(xn + rg * accN[r][c]);
            float hv = (1.f - ig) * ng + ig * hidden[(size_t)grow * 256 + col];
            out[9600 + (size_t)grow * 256 + col] = hv;
            hn[r][c] = hv;
        }
    }
#pragma unroll
    for (int r = 0; r < 2; r++)
#pragma unroll
        for (int c = 0; c < 16; c++) sB[c * 16 + tx][ty * 2 + r] = hn[r][c];
    __syncthreads();

    float accP[2][16];
    gemm32(Wo1, sB, sW, accP, tx, ty);
#pragma unroll
    for (int r = 0; r < 2; r++)
#pragma unroll
        for (int c = 0; c < 16; c++)
            sA[c * 16 + tx][ty * 2 + r] = fmaxf(accP[r][c] + bo1[c * 16 + tx], 0.f);
    __syncthreads();

    gemm32(Wo2, sA, sW, accP, tx, ty);
#pragma unroll
    for (int r = 0; r < 2; r++)
#pragma unroll
        for (int c = 0; c < 16; c++)
            sB[c * 16 + tx][ty * 2 + r] = fmaxf(accP[r][c] + bo2[c * 16 + tx], 0.f);
    __syncthreads();

    if (tid < 192) {
        int row = tid / 6, d = tid - (tid / 6) * 6;
        float s = bo3[d];
        const float* w = Wo3 + (size_t)d * 256;
        for (int k = 0; k < 256; k++) s += sB[k][row] * w[k];
        int grow = row0 + row;
        out[(size_t)grow * 6 + d] = inputs[(size_t)grow * 6 + d] + s;
    }
}

// ---------------------------------------------------------------------------
extern "C" void kernel_launch(void* const* d_in, const int* in_sizes, int n_in,
                              void* d_out, int out_size) {
    const float* inputs = (const float*)d_in[0];
    const float* hidden = (const float*)d_in[1];
    const float* edges  = (const float*)d_in[2];
    const float* W1     = (const float*)d_in[3];
    const float* b1     = (const float*)d_in[4];
    const float* W2     = (const float*)d_in[5];
    const float* b2     = (const float*)d_in[6];
    const float* Whr    = (const float*)d_in[7];
    const float* Whi    = (const float*)d_in[8];
    const float* Whh    = (const float*)d_in[9];
    const float* Wir    = (const float*)d_in[10];
    const float* bir    = (const float*)d_in[11];
    const float* Wii    = (const float*)d_in[12];
    const float* bii    = (const float*)d_in[13];
    const float* Win    = (const float*)d_in[14];
    const float* binw   = (const float*)d_in[15];
    const float* Wo1    = (const float*)d_in[16];
    const float* bo1    = (const float*)d_in[17];
    const float* Wo2    = (const float*)d_in[18];
    const float* bo2    = (const float*)d_in[19];
    const float* Wo3    = (const float*)d_in[20];
    const float* bo3    = (const float*)d_in[21];
    float* out = (float*)d_out;

    const size_t smem1 = (size_t)(256 * 65 + 16 * 256) * 4;           // 82944
    const size_t smem2 = smem1 + (size_t)(192 + 768) * 4;             // 86784
    const size_t smem4 = (size_t)(2 * 256 * 33 + 16 * 256 + 192) * 4; // 84736

    cudaFuncSetAttribute(k1_proj, cudaFuncAttributeMaxDynamicSharedMemorySize, (int)smem1);
    cudaFuncSetAttribute(k2_msg,  cudaFuncAttributeMaxDynamicSharedMemorySize, (int)smem2);
    cudaFuncSetAttribute(k4_gru,  cudaFuncAttributeMaxDynamicSharedMemorySize, (int)smem4);

    k1_proj<<<dim3(25, 6), 256, smem1>>>(hidden, W1, b1);
    k2_msg<<<dim3(39, 32), 256, smem2>>>(edges, W2, b2);
    k3_agg<<<1600, 256>>>();
    k4_gru<<<50, 256, smem4>>>(inputs, hidden, Whr, Whi, Whh,
                               Wir, bir, Wii, bii, Win, binw,
                               Wo1, bo1, Wo2, bo2, Wo3, bo3, out);
}

// round 3
// speedup vs baseline: 1.0493x; 1.0493x over previous
#include <cuda_runtime.h>
#include <math.h>

// Problem constants
#define BB 32
#define VV 50
#define DD 6
#define HH 256
#define TT 3            // edge types used (skip_first)
#define EE 2450         // V*(V-1)
#define NBV 1600        // B*V

// Scratch (device globals — allocation-free)
__device__ float g_P[(size_t)NBV * TT * 2 * HH];      // [row][t][dir][h], dir0=recv(+b1), dir1=send
__device__ float g_msg[(size_t)BB * EE * HH];         // per-edge messages summed over types (ew applied)
__device__ float g_agg[(size_t)NBV * HH];             // aggregated per node

// ---------------------------------------------------------------------------
// K1: node projections.  C[1600, 1536] = hidden[1600,256] @ W1-slices^T
// grid (25, 6): blockIdx.y -> (t, dir).  64 rows x 256 cols per block.
// ---------------------------------------------------------------------------
__global__ void __launch_bounds__(256, 1)
k1_proj(const float* __restrict__ hidden, const float* __restrict__ W1,
        const float* __restrict__ b1) {
    extern __shared__ float sm[];
    float (*sAT)[65] = (float(*)[65])sm;                   // [256][65] A transposed
    float (*sW)[256] = (float(*)[256])(sm + 256 * 65);     // [16][256]

    const int tid = threadIdx.x;
    const int tx = tid & 15, ty = tid >> 4;
    const int row0 = blockIdx.x * 64;
    const int nt = blockIdx.y;
    const int t = nt >> 1, dir = nt & 1;

    for (int i = tid; i < 64 * 256; i += 256) {
        int k = i & 255, r = i >> 8;
        sAT[k][r] = hidden[(size_t)(row0 + r) * 256 + k];
    }
    __syncthreads();

    float acc[4][16];
#pragma unroll
    for (int r = 0; r < 4; r++)
#pragma unroll
        for (int c = 0; c < 16; c++) acc[r][c] = 0.f;

    const float* wbase = W1 + ((size_t)t * 256 + tid) * 512 + dir * 256;

    for (int kc = 0; kc < 256; kc += 16) {
        const float4* wp = reinterpret_cast<const float4*>(wbase + kc);
        float4 q0 = wp[0], q1 = wp[1], q2 = wp[2], q3 = wp[3];
        sW[0][tid] = q0.x; sW[1][tid] = q0.y; sW[2][tid] = q0.z; sW[3][tid] = q0.w;
        sW[4][tid] = q1.x; sW[5][tid] = q1.y; sW[6][tid] = q1.z; sW[7][tid] = q1.w;
        sW[8][tid] = q2.x; sW[9][tid] = q2.y; sW[10][tid] = q2.z; sW[11][tid] = q2.w;
        sW[12][tid] = q3.x; sW[13][tid] = q3.y; sW[14][tid] = q3.z; sW[15][tid] = q3.w;
        __syncthreads();
#pragma unroll
        for (int kk = 0; kk < 16; ++kk) {
            float a0 = sAT[kc + kk][ty * 4 + 0];
            float a1 = sAT[kc + kk][ty * 4 + 1];
            float a2 = sAT[kc + kk][ty * 4 + 2];
            float a3 = sAT[kc + kk][ty * 4 + 3];
#pragma unroll
            for (int c = 0; c < 16; c++) {
                float w = sW[kk][c * 16 + tx];
                acc[0][c] += a0 * w; acc[1][c] += a1 * w;
                acc[2][c] += a2 * w; acc[3][c] += a3 * w;
            }
        }
        __syncthreads();
    }

#pragma unroll
    for (int r = 0; r < 4; r++) {
        int row = row0 + ty * 4 + r;
        float* outp = g_P + (((size_t)row * TT + t) * 2 + dir) * 256;
#pragma unroll
        for (int c = 0; c < 16; c++) {
            int col = c * 16 + tx;
            float v = acc[r][c];
            if (dir == 0) v += b1[t * 256 + col];
            outp[col] = v;
        }
    }
}

// ---------------------------------------------------------------------------
// K2: per-edge layer1(tanh) + layer2 GEMM + tanh + edge-weight, summed over t.
// grid (39, 32): 64-edge tile x batch.  Writes g_msg[b][e][h].
// ---------------------------------------------------------------------------
__global__ void __launch_bounds__(256, 1)
k2_msg(const float* __restrict__ edges, const float* __restrict__ W2,
       const float* __restrict__ b2) {
    extern __shared__ float sm[];
    float (*sAT)[65] = (float(*)[65])sm;                   // h1 transposed [256][65]
    float (*sW)[256] = (float(*)[256])(sm + 256 * 65);
    float* sEw = sm + 256 * 65 + 16 * 256;                 // [3][64]
    float* sB2 = sEw + 192;                                // [768]

    const int tid = threadIdx.x;
    const int tx = tid & 15, ty = tid >> 4;
    const int b = blockIdx.y;
    const int e0 = blockIdx.x * 64;

    for (int i = tid; i < 192; i += 256) {
        int t = i / 64, el = i - t * 64;
        int e = e0 + el;
        sEw[i] = (e < EE) ? edges[((size_t)b * EE + e) * 4 + 1 + t] : 0.f;
    }
    for (int i = tid; i < 768; i += 256) sB2[i] = b2[i];
    __syncthreads();

    float msgacc[4][16];
#pragma unroll
    for (int r = 0; r < 4; r++)
#pragma unroll
        for (int c = 0; c < 16; c++) msgacc[r][c] = 0.f;

    for (int t = 0; t < TT; t++) {
        // build h1 tile (transposed)
        for (int i = tid; i < 64 * 256; i += 256) {
            int h = i & 255, el = i >> 8;
            int e = e0 + el;
            float v = 0.f;
            if (e < EE) {
                int s = e / 49;
                int j = e - s * 49;
                int vr = j + (j >= s);
                const float* pr = g_P + (((size_t)(b * VV + vr) * TT + t) * 2 + 0) * 256;
                const float* ps = g_P + (((size_t)(b * VV + s) * TT + t) * 2 + 1) * 256;
                v = tanhf(pr[h] + ps[h]);
            }
            sAT[h][el] = v;
        }
        __syncthreads();

        float acc[4][16];
#pragma unroll
        for (int r = 0; r < 4; r++)
#pragma unroll
            for (int c = 0; c < 16; c++) acc[r][c] = 0.f;

        const float* wbase = W2 + ((size_t)t * 256 + tid) * 256;
        for (int kc = 0; kc < 256; kc += 16) {
            const float4* wp = reinterpret_cast<const float4*>(wbase + kc);
            float4 q0 = wp[0], q1 = wp[1], q2 = wp[2], q3 = wp[3];
            sW[0][tid] = q0.x; sW[1][tid] = q0.y; sW[2][tid] = q0.z; sW[3][tid] = q0.w;
            sW[4][tid] = q1.x; sW[5][tid] = q1.y; sW[6][tid] = q1.z; sW[7][tid] = q1.w;
            sW[8][tid] = q2.x; sW[9][tid] = q2.y; sW[10][tid] = q2.z; sW[11][tid] = q2.w;
            sW[12][tid] = q3.x; sW[13][tid] = q3.y; sW[14][tid] = q3.z; sW[15][tid] = q3.w;
            __syncthreads();
#pragma unroll
            for (int kk = 0; kk < 16; ++kk) {
                float a0 = sAT[kc + kk][ty * 4 + 0];
                float a1 = sAT[kc + kk][ty * 4 + 1];
                float a2 = sAT[kc + kk][ty * 4 + 2];
                float a3 = sAT[kc + kk][ty * 4 + 3];
#pragma unroll
                for (int c = 0; c < 16; c++) {
                    float w = sW[kk][c * 16 + tx];
                    acc[0][c] += a0 * w; acc[1][c] += a1 * w;
                    acc[2][c] += a2 * w; acc[3][c] += a3 * w;
                }
            }
            __syncthreads();
        }

#pragma unroll
        for (int r = 0; r < 4; r++) {
            float ew = sEw[t * 64 + ty * 4 + r];
#pragma unroll
            for (int c = 0; c < 16; c++) {
                int col = c * 16 + tx;
                msgacc[r][c] += tanhf(acc[r][c] + sB2[t * 256 + col]) * ew;
            }
        }
        __syncthreads();   // before rebuilding sAT for next t
    }

#pragma unroll
    for (int r = 0; r < 4; r++) {
        int e = e0 + ty * 4 + r;
        if (e < EE) {
            float* o = g_msg + ((size_t)b * EE + e) * 256;
#pragma unroll
            for (int c = 0; c < 16; c++) o[c * 16 + tx] = msgacc[r][c];
        }
    }
}

// ---------------------------------------------------------------------------
// K3: aggregate incoming edges per node.  grid 1600, 256 threads.
// ---------------------------------------------------------------------------
__global__ void k3_agg() {
    const int bv = blockIdx.x;
    const int b = bv / VV, v = bv - b * VV;
    const int h = threadIdx.x;
    const float* base = g_msg + (size_t)b * EE * 256;
    float s = 0.f;
    for (int snd = 0; snd < VV; ++snd) {
        if (snd == v) continue;
        int j = (v < snd) ? v : v - 1;
        s += base[(size_t)(snd * 49 + j) * 256 + h];
    }
    g_agg[(size_t)bv * 256 + h] = s * (1.f / 147.f);   // /norm(3) /(V-1)(49)
}

// ---------------------------------------------------------------------------
// K4: fused GRU update + output MLP. 32-row tiles, 5 smem GEMMs.
// ---------------------------------------------------------------------------
__device__ __forceinline__ void gemm32(const float* __restrict__ W,
                                       const float (*sAT)[33],
                                       float (*sW)[256],
                                       float acc[2][16], int tx, int ty) {
#pragma unroll
    for (int r = 0; r < 2; r++)
#pragma unroll
        for (int c = 0; c < 16; c++) acc[r][c] = 0.f;
    const float* wbase = W + (size_t)threadIdx.x * 256;
    for (int kc = 0; kc < 256; kc += 16) {
        const float4* wp = reinterpret_cast<const float4*>(wbase + kc);
        float4 q0 = wp[0], q1 = wp[1], q2 = wp[2], q3 = wp[3];
        sW[0][threadIdx.x] = q0.x; sW[1][threadIdx.x] = q0.y;
        sW[2][threadIdx.x] = q0.z; sW[3][threadIdx.x] = q0.w;
        sW[4][threadIdx.x] = q1.x; sW[5][threadIdx.x] = q1.y;
        sW[6][threadIdx.x] = q1.z; sW[7][threadIdx.x] = q1.w;
        sW[8][threadIdx.x] = q2.x; sW[9][threadIdx.x] = q2.y;
        sW[10][threadIdx.x] = q2.z; sW[11][threadIdx.x] = q2.w;
        sW[12][threadIdx.x] = q3.x; sW[13][threadIdx.x] = q3.y;
        sW[14][threadIdx.x] = q3.z; sW[15][threadIdx.x] = q3.w;
        __syncthreads();
#pragma unroll
        for (int kk = 0; kk < 16; ++kk) {
            float a0 = sAT[kc + kk][ty * 2 + 0];
            float a1 = sAT[kc + kk][ty * 2 + 1];
#pragma unroll
            for (int c = 0; c < 16; c++) {
                float w = sW[kk][c * 16 + tx];
                acc[0][c] += a0 * w;
                acc[1][c] += a1 * w;
            }
        }
        __syncthreads();
    }
}

__global__ void __launch_bounds__(256, 1)
k4_gru(const float* __restrict__ inputs, const float* __restrict__ hidden,
       const float* __restrict__ Whr, const float* __restrict__ Whi,
       const float* __restrict__ Whh,
       const float* __restrict__ Wir, const float* __restrict__ bir,
       const float* __restrict__ Wii, const float* __restrict__ bii,
       const float* __restrict__ Win, const float* __restrict__ binw,
       const float* __restrict__ Wo1, const float* __restrict__ bo1,
       const float* __restrict__ Wo2, const float* __restrict__ bo2,
       const float* __restrict__ Wo3, const float* __restrict__ bo3,
       float* __restrict__ out) {
    extern __shared__ float sm[];
    float (*sA)[33] = (float(*)[33])sm;                       // [256][33]
    float (*sB)[33] = (float(*)[33])(sm + 256 * 33);          // [256][33]
    float (*sW)[256] = (float(*)[256])(sm + 2 * 256 * 33);    // [16][256]
    float* sX = sm + 2 * 256 * 33 + 16 * 256;                 // [32*6]

    const int tid = threadIdx.x;
    const int tx = tid & 15, ty = tid >> 4;
    const int row0 = blockIdx.x * 32;

    for (int i = tid; i < 32 * 256; i += 256) {
        int k = i & 255, r = i >> 8;
        sA[k][r] = g_agg[(size_t)(row0 + r) * 256 + k];
    }
    if (tid < 192) sX[tid] = inputs[(size_t)row0 * 6 + tid];
    __syncthreads();

    float accR[2][16], accI[2][16], accN[2][16];
    gemm32(Whr, sA, sW, accR, tx, ty);
    gemm32(Whi, sA, sW, accI, tx, ty);
    gemm32(Whh, sA, sW, accN, tx, ty);

    float hn[2][16];
#pragma unroll
    for (int r = 0; r < 2; r++) {
        int row = ty * 2 + r;
        int grow = row0 + row;
#pragma unroll
        for (int c = 0; c < 16; c++) {
            int col = c * 16 + tx;
            float xr = bir[col], xi = bii[col], xn = binw[col];
#pragma unroll
            for (int d = 0; d < 6; d++) {
                float xd = sX[row * 6 + d];
                xr += Wir[col * 6 + d] * xd;
                xi += Wii[col * 6 + d] * xd;
                xn += Win[col * 6 + d] * xd;
            }
            float rg = 1.f / (1.f + expf(-(accR[r][c] + xr)));
            float ig = 1.f / (1.f + expf(-(accI[r][c] + xi)));
            float ng = tanhf(xn + rg * accN[r][c]);
            float hv = (1.f - ig) * ng + ig * hidden[(size_t)grow * 256 + col];
            out[9600 + (size_t)grow * 256 + col] = hv;
            hn[r][c] = hv;
        }
    }
#pragma unroll
    for (int r = 0; r < 2; r++)
#pragma unroll
        for (int c = 0; c < 16; c++) sB[c * 16 + tx][ty * 2 + r] = hn[r][c];
    __syncthreads();

    float accP[2][16];
    gemm32(Wo1, sB, sW, accP, tx, ty);
#pragma unroll
    for (int r = 0; r < 2; r++)
#pragma unroll
        for (int c = 0; c < 16; c++)
            sA[c * 16 + tx][ty * 2 + r] = fmaxf(accP[r][c] + bo1[c * 16 + tx], 0.f);
    __syncthreads();

    gemm32(Wo2, sA, sW, accP, tx, ty);
#pragma unroll
    for (int r = 0; r < 2; r++)
#pragma unroll
        for (int c = 0; c < 16; c++)
            sB[c * 16 + tx][ty * 2 + r] = fmaxf(accP[r][c] + bo2[c * 16 + tx], 0.f);
    __syncthreads();

    if (tid < 192) {
        int row = tid / 6, d = tid - (tid / 6) * 6;
        float s = bo3[d];
        const float* w = Wo3 + (size_t)d * 256;
        for (int k = 0; k < 256; k++) s += sB[k][row] * w[k];
        int grow = row0 + row;
        out[(size_t)grow * 6 + d] = inputs[(size_t)grow * 6 + d] + s;
    }
}

// ---------------------------------------------------------------------------
extern "C" void kernel_launch(void* const* d_in, const int* in_sizes, int n_in,
                              void* d_out, int out_size) {
    const float* inputs = (const float*)d_in[0];
    const float* hidden = (const float*)d_in[1];
    const float* edges  = (const float*)d_in[2];
    const float* W1     = (const float*)d_in[3];
    const float* b1     = (const float*)d_in[4];
    const float* W2     = (const float*)d_in[5];
    const float* b2     = (const float*)d_in[6];
    const float* Whr    = (const float*)d_in[7];
    const float* Whi    = (const float*)d_in[8];
    const float* Whh    = (const float*)d_in[9];
    const float* Wir    = (const float*)d_in[10];
    const float* bir    = (const float*)d_in[11];
    const float* Wii    = (const float*)d_in[12];
    const float* bii    = (const float*)d_in[13];
    const float* Win    = (const float*)d_in[14];
    const float* binw   = (const float*)d_in[15];
    const float* Wo1    = (const float*)d_in[16];
    const float* bo1    = (const float*)d_in[17];
    const float* Wo2    = (const float*)d_in[18];
    const float* bo2    = (const float*)d_in[19];
    const float* Wo3    = (const float*)d_in[20];
    const float* bo3    = (const float*)d_in[21];
    float* out = (float*)d_out;

    const size_t smem1 = (size_t)(256 * 65 + 16 * 256) * 4;           // 82944
    const size_t smem2 = smem1 + (size_t)(192 + 768) * 4;             // 86784
    const size_t smem4 = (size_t)(2 * 256 * 33 + 16 * 256 + 192) * 4; // 84736

    cudaFuncSetAttribute(k1_proj, cudaFuncAttributeMaxDynamicSharedMemorySize, (int)smem1);
    cudaFuncSetAttribute(k2_msg,  cudaFuncAttributeMaxDynamicSharedMemorySize, (int)smem2);
    cudaFuncSetAttribute(k4_gru,  cudaFuncAttributeMaxDynamicSharedMemorySize, (int)smem4);

    k1_proj<<<dim3(25, 6), 256, smem1>>>(hidden, W1, b1);
    k2_msg<<<dim3(39, 32), 256, smem2>>>(edges, W2, b2);
    k3_agg<<<1600, 256>>>();
    k4_gru<<<50, 256, smem4>>>(inputs, hidden, Whr, Whi, Whh,
                               Wir, bir, Wii, bii, Win, binw,
                               Wo1, bo1, Wo2, bo2, Wo3, bo3, out);
}

// round 6
// speedup vs baseline: 3.0281x; 2.8859x over previous
#include <cuda_runtime.h>
#include <cstdint>
#include <math.h>

#define BB 32
#define VV 50
#define EE 2450
#define NBV 1600

__device__ float g_P[(size_t)NBV * 1536];          // k1 out; later k4 scratch (5 x 409600)
__device__ float g_msg[(size_t)BB * EE * 256];
__device__ float g_agg[(size_t)NBV * 256];

// single dynamic-smem symbol (k1 only)
extern __shared__ char s_dyn[];

// ===================== helpers =====================
__device__ __forceinline__ float ftanh(float x) {
    float y; asm("tanh.approx.f32 %0, %1;" : "=f"(y) : "f"(x)); return y;
}
__device__ __forceinline__ uint32_t to_tf32(float x) {
    uint32_t u; asm("cvt.rna.tf32.f32 %0, %1;" : "=r"(u) : "f"(x)); return u;
}
__device__ __forceinline__ void mma1688(float d[4],
                                        uint32_t a0, uint32_t a1, uint32_t a2, uint32_t a3,
                                        uint32_t b0, uint32_t b1) {
    asm volatile(
        "mma.sync.aligned.m16n8k8.row.col.f32.tf32.tf32.f32 "
        "{%0,%1,%2,%3}, {%4,%5,%6,%7}, {%8,%9}, {%0,%1,%2,%3};"
        : "+f"(d[0]), "+f"(d[1]), "+f"(d[2]), "+f"(d[3])
        : "r"(a0), "r"(a1), "r"(a2), "r"(a3), "r"(b0), "r"(b1));
}

// ===================== K1: node projections (fp32) =====================
__global__ void __launch_bounds__(256, 1)
k1_proj(const float* __restrict__ hidden, const float* __restrict__ W1,
        const float* __restrict__ b1) {
    float* sm = (float*)s_dyn;
    float (*sAT)[65] = (float(*)[65])sm;
    float (*sW)[256] = (float(*)[256])(sm + 256 * 65);
    const int tid = threadIdx.x, tx = tid & 15, ty = tid >> 4;
    const int row0 = blockIdx.x * 64;
    const int t = blockIdx.y >> 1, dir = blockIdx.y & 1;

    for (int i = tid; i < 64 * 256; i += 256) {
        int k = i & 255, r = i >> 8;
        sAT[k][r] = hidden[(size_t)(row0 + r) * 256 + k];
    }
    __syncthreads();
    float acc[4][16];
#pragma unroll
    for (int r = 0; r < 4; r++)
#pragma unroll
        for (int c = 0; c < 16; c++) acc[r][c] = 0.f;
    const float* wbase = W1 + ((size_t)t * 256 + tid) * 512 + dir * 256;
    for (int kc = 0; kc < 256; kc += 16) {
        const float4* wp = (const float4*)(wbase + kc);
        float4 q0 = wp[0], q1 = wp[1], q2 = wp[2], q3 = wp[3];
        sW[0][tid]=q0.x; sW[1][tid]=q0.y; sW[2][tid]=q0.z; sW[3][tid]=q0.w;
        sW[4][tid]=q1.x; sW[5][tid]=q1.y; sW[6][tid]=q1.z; sW[7][tid]=q1.w;
        sW[8][tid]=q2.x; sW[9][tid]=q2.y; sW[10][tid]=q2.z; sW[11][tid]=q2.w;
        sW[12][tid]=q3.x; sW[13][tid]=q3.y; sW[14][tid]=q3.z; sW[15][tid]=q3.w;
        __syncthreads();
#pragma unroll
        for (int kk = 0; kk < 16; ++kk) {
            float a0 = sAT[kc+kk][ty*4+0], a1 = sAT[kc+kk][ty*4+1];
            float a2 = sAT[kc+kk][ty*4+2], a3 = sAT[kc+kk][ty*4+3];
#pragma unroll
            for (int c = 0; c < 16; c++) {
                float w = sW[kk][c*16+tx];
                acc[0][c]+=a0*w; acc[1][c]+=a1*w; acc[2][c]+=a2*w; acc[3][c]+=a3*w;
            }
        }
        __syncthreads();
    }
#pragma unroll
    for (int r = 0; r < 4; r++) {
        int row = row0 + ty*4 + r;
        float* outp = g_P + (((size_t)row * 3 + t) * 2 + dir) * 256;
#pragma unroll
        for (int c = 0; c < 16; c++) {
            int col = c*16+tx;
            float v = acc[r][c];
            if (dir == 0) v += b1[t*256+col];
            outp[col] = v;
        }
    }
}

// ===================== K2: tf32 mma.sync message kernel =====================
// block = 128 edges x 128 cols, grid (20, 2, 32). 8 warps: 4(m) x 2(n), warp tile 32x64.
#define APAD 36
__global__ void __launch_bounds__(256, 1)
k2_msg(const float* __restrict__ edges, const float* __restrict__ W2,
       const float* __restrict__ b2) {
    __shared__ uint32_t As[128][APAD];     // [edge-row][k] tf32
    __shared__ uint32_t Bs[128][APAD];     // [col][k] tf32
    __shared__ float sEw[384];             // [3][128] edge weights
    __shared__ float sB2[384];             // [3][128] bias slice

    const int tid = threadIdx.x;
    const int wid = tid >> 5, lane = tid & 31;
    const int gid = lane >> 2, tig = lane & 3;
    const int wm = wid & 3, wn = wid >> 2;
    const int e0 = blockIdx.x * 128;
    const int ch = blockIdx.y;             // column half (128 cols)
    const int b  = blockIdx.z;

    for (int i = tid; i < 384; i += 256) {
        int t = i >> 7, r = i & 127;
        int e = e0 + r;
        sEw[i] = (e < EE) ? edges[((size_t)b * EE + e) * 4 + 1 + t] : 0.f;
        sB2[i] = b2[t * 256 + ch * 128 + r];
    }

    float macc[2][8][4];
#pragma unroll
    for (int mt = 0; mt < 2; mt++)
#pragma unroll
        for (int nt = 0; nt < 8; nt++)
#pragma unroll
            for (int c = 0; c < 4; c++) macc[mt][nt][c] = 0.f;

    for (int t = 0; t < 3; t++) {
        float acc[2][8][4];
#pragma unroll
        for (int mt = 0; mt < 2; mt++)
#pragma unroll
            for (int nt = 0; nt < 8; nt++)
#pragma unroll
                for (int c = 0; c < 4; c++) acc[mt][nt][c] = 0.f;

        for (int kc = 0; kc < 256; kc += 32) {
            __syncthreads();   // previous iteration's frag loads done
            // build A: tanh(Pr + Ps), tf32
#pragma unroll
            for (int i = tid; i < 1024; i += 256) {
                int row = i >> 3, q = i & 7, k0 = q * 4;
                int e = e0 + row;
                uint4 u = {0u, 0u, 0u, 0u};
                if (e < EE) {
                    int s = e / 49, j = e - s * 49;
                    int vr = j + (j >= s);
                    float4 pr = *(const float4*)(g_P + (((size_t)(b*VV+vr)*3 + t)*2 + 0)*256 + kc + k0);
                    float4 ps = *(const float4*)(g_P + (((size_t)(b*VV+s )*3 + t)*2 + 1)*256 + kc + k0);
                    u.x = to_tf32(ftanh(pr.x + ps.x));
                    u.y = to_tf32(ftanh(pr.y + ps.y));
                    u.z = to_tf32(ftanh(pr.z + ps.z));
                    u.w = to_tf32(ftanh(pr.w + ps.w));
                }
                *(uint4*)&As[row][k0] = u;
            }
            // build B: W2 slice, tf32
#pragma unroll
            for (int i = tid; i < 1024; i += 256) {
                int n = i >> 3, q = i & 7, k0 = q * 4;
                float4 w = *(const float4*)(W2 + ((size_t)t * 256 + ch * 128 + n) * 256 + kc + k0);
                uint4 u;
                u.x = to_tf32(w.x); u.y = to_tf32(w.y); u.z = to_tf32(w.z); u.w = to_tf32(w.w);
                *(uint4*)&Bs[n][k0] = u;
            }
            __syncthreads();
#pragma unroll
            for (int ks = 0; ks < 4; ks++) {
                int k = ks * 8;
                uint32_t a[2][4];
#pragma unroll
                for (int mt = 0; mt < 2; mt++) {
                    int row = wm * 32 + mt * 16 + gid;
                    a[mt][0] = As[row][k + tig];
                    a[mt][1] = As[row + 8][k + tig];
                    a[mt][2] = As[row][k + tig + 4];
                    a[mt][3] = As[row + 8][k + tig + 4];
                }
#pragma unroll
                for (int nt = 0; nt < 8; nt++) {
                    int n = wn * 64 + nt * 8 + gid;
                    uint32_t b0 = Bs[n][k + tig];
                    uint32_t b1 = Bs[n][k + tig + 4];
                    mma1688(acc[0][nt], a[0][0], a[0][1], a[0][2], a[0][3], b0, b1);
                    mma1688(acc[1][nt], a[1][0], a[1][1], a[1][2], a[1][3], b0, b1);
                }
            }
        }
        // epilogue for type t
#pragma unroll
        for (int mt = 0; mt < 2; mt++) {
            int rl = wm * 32 + mt * 16 + gid;
            float ew0 = sEw[t * 128 + rl];
            float ew1 = sEw[t * 128 + rl + 8];
#pragma unroll
            for (int nt = 0; nt < 8; nt++) {
                int c0 = wn * 64 + nt * 8 + 2 * tig;
                float bb0 = sB2[t * 128 + c0];
                float bb1 = sB2[t * 128 + c0 + 1];
                macc[mt][nt][0] += ftanh(acc[mt][nt][0] + bb0) * ew0;
                macc[mt][nt][1] += ftanh(acc[mt][nt][1] + bb1) * ew0;
                macc[mt][nt][2] += ftanh(acc[mt][nt][2] + bb0) * ew1;
                macc[mt][nt][3] += ftanh(acc[mt][nt][3] + bb1) * ew1;
            }
        }
    }
    // store: c0,c1 at (row, col..col+1); c2,c3 at (row+8, ...)
#pragma unroll
    for (int mt = 0; mt < 2; mt++) {
        int rl = wm * 32 + mt * 16 + gid;
        int eA = e0 + rl, eB = e0 + rl + 8;
#pragma unroll
        for (int nt = 0; nt < 8; nt++) {
            int col = ch * 128 + wn * 64 + nt * 8 + 2 * tig;
            if (eA < EE)
                *(float2*)(g_msg + ((size_t)b * EE + eA) * 256 + col)
                    = make_float2(macc[mt][nt][0], macc[mt][nt][1]);
            if (eB < EE)
                *(float2*)(g_msg + ((size_t)b * EE + eB) * 256 + col)
                    = make_float2(macc[mt][nt][2], macc[mt][nt][3]);
        }
    }
}

// ===================== K3: aggregate =====================
__global__ void k3_agg() {
    const int bv = blockIdx.x;
    const int b = bv / VV, v = bv - b * VV;
    const int h = threadIdx.x;
    const float* base = g_msg + (size_t)b * EE * 256;
    float s = 0.f;
    for (int snd = 0; snd < VV; ++snd) {
        if (snd == v) continue;
        int j = (v < snd) ? v : v - 1;
        s += base[(size_t)(snd * 49 + j) * 256 + h];
    }
    g_agg[(size_t)bv * 256 + h] = s * (1.f / 147.f);
}

// ===================== K4: generic 32x128 GEMM tile =====================
__global__ void __launch_bounds__(256, 2)
kgemm(const float* __restrict__ A,
      const float* __restrict__ W0, const float* __restrict__ W1m, const float* __restrict__ W2m,
      const float* __restrict__ bi0, const float* __restrict__ bi1, const float* __restrict__ bi2,
      float* __restrict__ o0, float* __restrict__ o1, float* __restrict__ o2,
      int act) {
    __shared__ float sA[256][33];
    __shared__ float sW[16][128];
    const int tid = threadIdx.x, tx = tid & 15, ty = tid >> 4;
    const int row0 = blockIdx.x * 32;
    const int ch = blockIdx.y;
    const int m = blockIdx.z;
    const float* W = (m == 0) ? W0 : (m == 1) ? W1m : W2m;
    const float* bi = (m == 0) ? bi0 : (m == 1) ? bi1 : bi2;
    float* o = (m == 0) ? o0 : (m == 1) ? o1 : o2;

    for (int i = tid; i < 32 * 256; i += 256) {
        int k = i & 255, r = i >> 8;
        sA[k][r] = A[(size_t)(row0 + r) * 256 + k];
    }
    __syncthreads();
    float acc[2][8];
#pragma unroll
    for (int r = 0; r < 2; r++)
#pragma unroll
        for (int c = 0; c < 8; c++) acc[r][c] = 0.f;

    const int lcol = tid & 127, half = tid >> 7;
    const float* wrow = W + (size_t)(ch * 128 + lcol) * 256;
    for (int kc = 0; kc < 256; kc += 16) {
        float4 q0 = *(const float4*)(wrow + kc + half * 8);
        float4 q1 = *(const float4*)(wrow + kc + half * 8 + 4);
        sW[half*8+0][lcol]=q0.x; sW[half*8+1][lcol]=q0.y; sW[half*8+2][lcol]=q0.z; sW[half*8+3][lcol]=q0.w;
        sW[half*8+4][lcol]=q1.x; sW[half*8+5][lcol]=q1.y; sW[half*8+6][lcol]=q1.z; sW[half*8+7][lcol]=q1.w;
        __syncthreads();
#pragma unroll
        for (int kk = 0; kk < 16; ++kk) {
            float a0 = sA[kc+kk][ty*2+0], a1 = sA[kc+kk][ty*2+1];
#pragma unroll
            for (int c = 0; c < 8; c++) {
                float w = sW[kk][c*16+tx];
                acc[0][c] += a0 * w;
                acc[1][c] += a1 * w;
            }
        }
        __syncthreads();
    }
#pragma unroll
    for (int r = 0; r < 2; r++) {
        int grow = row0 + ty*2 + r;
#pragma unroll
        for (int c = 0; c < 8; c++) {
            int gcol = ch * 128 + c*16+tx;
            float v = acc[r][c];
            if (bi) v += bi[gcol];
            if (act) v = fmaxf(v, 0.f);
            o[(size_t)grow * 256 + gcol] = v;
        }
    }
}

// ===================== K4b: gates =====================
__global__ void kgate(const float* __restrict__ inputs, const float* __restrict__ hidden,
                      const float* __restrict__ SR, const float* __restrict__ SI,
                      const float* __restrict__ SN,
                      const float* __restrict__ Wir, const float* __restrict__ bir,
                      const float* __restrict__ Wii, const float* __restrict__ bii,
                      const float* __restrict__ Win, const float* __restrict__ binw,
                      float* __restrict__ out) {
    const int row = blockIdx.x, col = threadIdx.x;
    __shared__ float x[6];
    if (col < 6) x[col] = inputs[row * 6 + col];
    __syncthreads();
    float xr = bir[col], xi = bii[col], xn = binw[col];
#pragma unroll
    for (int d = 0; d < 6; d++) {
        float xd = x[d];
        xr += Wir[col*6+d] * xd; xi += Wii[col*6+d] * xd; xn += Win[col*6+d] * xd;
    }
    size_t idx = (size_t)row * 256 + col;
    float rg = 1.f / (1.f + expf(-(SR[idx] + xr)));
    float ig = 1.f / (1.f + expf(-(SI[idx] + xi)));
    float ng = tanhf(xn + rg * SN[idx]);
    out[9600 + idx] = (1.f - ig) * ng + ig * hidden[idx];
}

// ===================== K4e: prediction =====================
__global__ void kpred(const float* __restrict__ inputs, const float* __restrict__ p2,
                      const float* __restrict__ Wo3, const float* __restrict__ bo3,
                      float* __restrict__ out) {
    __shared__ float sP[32 * 257];
    __shared__ float sW3[6 * 256];
    const int tid = threadIdx.x;
    const int row0 = blockIdx.x * 32;
    for (int i = tid; i < 32 * 256; i += 256) {
        int r = i >> 8, k = i & 255;
        sP[r * 257 + k] = p2[(size_t)(row0 + r) * 256 + k];
    }
    for (int i = tid; i < 1536; i += 256) sW3[i] = Wo3[i];
    __syncthreads();
    if (tid < 192) {
        int row = tid / 6, d = tid - (tid / 6) * 6;
        float s = bo3[d];
        for (int k = 0; k < 256; k++) s += sP[row * 257 + k] * sW3[d * 256 + k];
        size_t g = (size_t)(row0 + row) * 6 + d;
        out[g] = inputs[g] + s;
    }
}

// ===================== launch =====================
extern "C" void kernel_launch(void* const* d_in, const int* in_sizes, int n_in,
                              void* d_out, int out_size) {
    const float* inputs = (const float*)d_in[0];
    const float* hidden = (const float*)d_in[1];
    const float* edges  = (const float*)d_in[2];
    const float* W1     = (const float*)d_in[3];
    const float* b1     = (const float*)d_in[4];
    const float* W2     = (const float*)d_in[5];
    const float* b2     = (const float*)d_in[6];
    const float* Whr    = (const float*)d_in[7];
    const float* Whi    = (const float*)d_in[8];
    const float* Whh    = (const float*)d_in[9];
    const float* Wir    = (const float*)d_in[10];
    const float* bir    = (const float*)d_in[11];
    const float* Wii    = (const float*)d_in[12];
    const float* bii    = (const float*)d_in[13];
    const float* Win    = (const float*)d_in[14];
    const float* binw   = (const float*)d_in[15];
    const float* Wo1    = (const float*)d_in[16];
    const float* bo1    = (const float*)d_in[17];
    const float* Wo2    = (const float*)d_in[18];
    const float* bo2    = (const float*)d_in[19];
    const float* Wo3    = (const float*)d_in[20];
    const float* bo3    = (const float*)d_in[21];
    float* out = (float*)d_out;

    void* pP = nullptr; void* pAgg = nullptr;
    cudaGetSymbolAddress(&pP, g_P);
    cudaGetSymbolAddress(&pAgg, g_agg);
    float* gp = (float*)pP;
    float* gagg = (float*)pAgg;
    float* SR = gp;                 // reuse g_P as k4 scratch (consumed by k2 already)
    float* SI = gp + 409600;
    float* SN = gp + 819200;
    float* P1 = gp + 1228800;
    float* P2 = gp + 1638400;

    const size_t smem1 = (size_t)(256 * 65 + 16 * 256) * 4;
    cudaFuncSetAttribute(k1_proj, cudaFuncAttributeMaxDynamicSharedMemorySize, (int)smem1);

    k1_proj<<<dim3(25, 6), 256, smem1>>>(hidden, W1, b1);
    k2_msg<<<dim3(20, 2, 32), 256>>>(edges, W2, b2);
    k3_agg<<<1600, 256>>>();
    kgemm<<<dim3(50, 2, 3), 256>>>(gagg, Whr, Whi, Whh,
                                   nullptr, nullptr, nullptr, SR, SI, SN, 0);
    kgate<<<1600, 256>>>(inputs, hidden, SR, SI, SN,
                         Wir, bir, Wii, bii, Win, binw, out);
    kgemm<<<dim3(50, 2, 1), 256>>>(out + 9600, Wo1, Wo1, Wo1,
                                   bo1, bo1, bo1, P1, P1, P1, 1);
    kgemm<<<dim3(50, 2, 1), 256>>>(P1, Wo2, Wo2, Wo2,
                                   bo2, bo2, bo2, P2, P2, P2, 1);
    kpred<<<50, 256>>>(inputs, P2, Wo3, bo3, out);
}

// round 7
// speedup vs baseline: 3.5898x; 1.1855x over previous
#include <cuda_runtime.h>
#include <cstdint>
#include <math.h>

#define BB 32
#define VV 50
#define EE 2450
#define NBV 1600

__device__ float g_P[(size_t)NBV * 1536];             // k1 out; later k4 scratch (5 x 409600)
__device__ float g_msg3[(size_t)3 * BB * EE * 256];   // per-type messages
__device__ float g_agg[(size_t)NBV * 256];

extern __shared__ char s_dyn[];

// ===================== helpers =====================
__device__ __forceinline__ float ftanh(float x) {
    float y; asm("tanh.approx.f32 %0, %1;" : "=f"(y) : "f"(x)); return y;
}
__device__ __forceinline__ uint32_t to_tf32(float x) {
    uint32_t u; asm("cvt.rna.tf32.f32 %0, %1;" : "=r"(u) : "f"(x)); return u;
}
__device__ __forceinline__ void mma1688(float d[4],
                                        uint32_t a0, uint32_t a1, uint32_t a2, uint32_t a3,
                                        uint32_t b0, uint32_t b1) {
    asm volatile(
        "mma.sync.aligned.m16n8k8.row.col.f32.tf32.tf32.f32 "
        "{%0,%1,%2,%3}, {%4,%5,%6,%7}, {%8,%9}, {%0,%1,%2,%3};"
        : "+f"(d[0]), "+f"(d[1]), "+f"(d[2]), "+f"(d[3])
        : "r"(a0), "r"(a1), "r"(a2), "r"(a3), "r"(b0), "r"(b1));
}
#define APAD 36

// ===================== K2: per-type tf32 message kernel =====================
// block = 128 edges x 256 cols x 1 type. grid (20, 32, 3). 8 warps 2m x 4n (warp 64x64).
#define K2_SMEM ((128 + 256) * APAD * 4 + (128 + 256) * 4)
__global__ void __launch_bounds__(256, 1)
k2_msg(const float* __restrict__ edges, const float* __restrict__ W2,
       const float* __restrict__ b2) {
    char* sm = s_dyn;
    uint32_t (*As)[APAD] = (uint32_t(*)[APAD])sm;                       // [128][36]
    uint32_t (*Bs)[APAD] = (uint32_t(*)[APAD])(sm + 128 * APAD * 4);    // [256][36]
    float* sEw = (float*)(sm + (128 + 256) * APAD * 4);                 // [128]
    float* sB2 = sEw + 128;                                             // [256]

    const int tid = threadIdx.x;
    const int wid = tid >> 5, lane = tid & 31;
    const int gid = lane >> 2, tig = lane & 3;
    const int wn = wid & 3, wm = wid >> 2;     // 2(m) x 4(n)
    const int e0 = blockIdx.x * 128;
    const int b  = blockIdx.y;
    const int t  = blockIdx.z;

    if (tid < 128) {
        int e = e0 + tid;
        sEw[tid] = (e < EE) ? edges[((size_t)b * EE + e) * 4 + 1 + t] : 0.f;
    }
    sB2[tid] = b2[t * 256 + tid];

    float acc[4][8][4];
#pragma unroll
    for (int mt = 0; mt < 4; mt++)
#pragma unroll
        for (int nt = 0; nt < 8; nt++)
#pragma unroll
            for (int c = 0; c < 4; c++) acc[mt][nt][c] = 0.f;

    const float* Pbase = g_P + (size_t)(t * 2) * 256;

    for (int kc = 0; kc < 256; kc += 32) {
        __syncthreads();   // frag loads of previous iter done
        // ---- A build: h1 = tanh(Pr + Ps) tf32, 128 x 32 ----
#pragma unroll
        for (int i = tid; i < 1024; i += 256) {
            int row = i >> 3, k0 = (i & 7) * 4;
            int e = e0 + row;
            uint4 u = {0u, 0u, 0u, 0u};
            if (e < EE) {
                int s = e / 49, j = e - s * 49;
                int vr = j + (j >= s);
                float4 pr = *(const float4*)(Pbase + (size_t)(b * VV + vr) * 1536 + kc + k0);
                float4 ps = *(const float4*)(Pbase + (size_t)(b * VV + s) * 1536 + 256 + kc + k0);
                u.x = to_tf32(ftanh(pr.x + ps.x));
                u.y = to_tf32(ftanh(pr.y + ps.y));
                u.z = to_tf32(ftanh(pr.z + ps.z));
                u.w = to_tf32(ftanh(pr.w + ps.w));
            }
            *(uint4*)&As[row][k0] = u;
        }
        // ---- B build: W2 slice tf32, 256 x 32 ----
#pragma unroll
        for (int i = tid; i < 2048; i += 256) {
            int n = i >> 3, k0 = (i & 7) * 4;
            float4 w = *(const float4*)(W2 + ((size_t)t * 256 + n) * 256 + kc + k0);
            uint4 u;
            u.x = to_tf32(w.x); u.y = to_tf32(w.y); u.z = to_tf32(w.z); u.w = to_tf32(w.w);
            *(uint4*)&Bs[n][k0] = u;
        }
        __syncthreads();
#pragma unroll
        for (int ks = 0; ks < 4; ks++) {
            int k = ks * 8;
            uint32_t a[4][4];
#pragma unroll
            for (int mt = 0; mt < 4; mt++) {
                int row = wm * 64 + mt * 16 + gid;
                a[mt][0] = As[row][k + tig];
                a[mt][1] = As[row + 8][k + tig];
                a[mt][2] = As[row][k + tig + 4];
                a[mt][3] = As[row + 8][k + tig + 4];
            }
#pragma unroll
            for (int nt = 0; nt < 8; nt++) {
                int n = wn * 64 + nt * 8 + gid;
                uint32_t b0 = Bs[n][k + tig];
                uint32_t b1 = Bs[n][k + tig + 4];
#pragma unroll
                for (int mt = 0; mt < 4; mt++)
                    mma1688(acc[mt][nt], a[mt][0], a[mt][1], a[mt][2], a[mt][3], b0, b1);
            }
        }
    }
    // ---- epilogue: msg = tanh(acc + b2) * ew, store to per-type buffer ----
    float* mout = g_msg3 + ((size_t)t * BB + b) * EE * 256;
#pragma unroll
    for (int mt = 0; mt < 4; mt++) {
        int rl = wm * 64 + mt * 16 + gid;
        int eA = e0 + rl, eB = eA + 8;
        float ewA = sEw[rl], ewB = sEw[rl + 8];
#pragma unroll
        for (int nt = 0; nt < 8; nt++) {
            int c0 = wn * 64 + nt * 8 + 2 * tig;
            float bb0 = sB2[c0], bb1 = sB2[c0 + 1];
            if (eA < EE)
                *(float2*)(mout + (size_t)eA * 256 + c0) =
                    make_float2(ftanh(acc[mt][nt][0] + bb0) * ewA,
                                ftanh(acc[mt][nt][1] + bb1) * ewA);
            if (eB < EE)
                *(float2*)(mout + (size_t)eB * 256 + c0) =
                    make_float2(ftanh(acc[mt][nt][2] + bb0) * ewB,
                                ftanh(acc[mt][nt][3] + bb1) * ewB);
        }
    }
}

// ===================== K3: aggregate over incoming edges + types =====================
__global__ void k3_agg() {
    const int bv = blockIdx.x;
    const int b = bv / VV, v = bv - b * VV;
    const int h = threadIdx.x;
    const size_t toff = (size_t)BB * EE * 256;
    const float* base = g_msg3 + (size_t)b * EE * 256;
    float s0 = 0.f, s1 = 0.f, s2 = 0.f;
    for (int snd = 0; snd < VV; ++snd) {
        if (snd == v) continue;
        int j = (v < snd) ? v : v - 1;
        size_t off = (size_t)(snd * 49 + j) * 256 + h;
        s0 += base[off];
        s1 += base[toff + off];
        s2 += base[2 * toff + off];
    }
    g_agg[(size_t)bv * 256 + h] = (s0 + s1 + s2) * (1.f / 147.f);
}

// ===================== generic tf32 mma GEMM: C = act(A @ W^T + bias) =====================
// block tile 128 x 128, 8 warps 2m x 4n (warp 64 x 32). per-z args.
struct GArg {
    const float* A;        // [M, 256]
    const float* W;        // rows at stride wld
    const float* bias;     // [128*gridDim.y] or null
    float* out;
    int wld, outld, outcol, act;
};
struct GArgs { GArg g[6]; };

__global__ void __launch_bounds__(256, 2)
kg_mma(GArgs args, int M) {
    __shared__ uint32_t As[128][APAD];
    __shared__ uint32_t Bs[128][APAD];
    const GArg ga = args.g[blockIdx.z];
    const int tid = threadIdx.x;
    const int wid = tid >> 5, lane = tid & 31;
    const int gid = lane >> 2, tig = lane & 3;
    const int wn = wid & 3, wm = wid >> 2;     // 2(m) x 4(n), warp 64x32
    const int row0 = blockIdx.x * 128;
    const int col0 = blockIdx.y * 128;

    float acc[4][4][4];
#pragma unroll
    for (int mt = 0; mt < 4; mt++)
#pragma unroll
        for (int nt = 0; nt < 4; nt++)
#pragma unroll
            for (int c = 0; c < 4; c++) acc[mt][nt][c] = 0.f;

    for (int kc = 0; kc < 256; kc += 32) {
        __syncthreads();
#pragma unroll
        for (int i = tid; i < 1024; i += 256) {
            int r = i >> 3, k0 = (i & 7) * 4;
            int row = row0 + r;
            uint4 u = {0u, 0u, 0u, 0u};
            if (row < M) {
                float4 a = *(const float4*)(ga.A + (size_t)row * 256 + kc + k0);
                u.x = to_tf32(a.x); u.y = to_tf32(a.y); u.z = to_tf32(a.z); u.w = to_tf32(a.w);
            }
            *(uint4*)&As[r][k0] = u;
        }
#pragma unroll
        for (int i = tid; i < 1024; i += 256) {
            int n = i >> 3, k0 = (i & 7) * 4;
            float4 w = *(const float4*)(ga.W + (size_t)(col0 + n) * ga.wld + kc + k0);
            uint4 u;
            u.x = to_tf32(w.x); u.y = to_tf32(w.y); u.z = to_tf32(w.z); u.w = to_tf32(w.w);
            *(uint4*)&Bs[n][k0] = u;
        }
        __syncthreads();
#pragma unroll
        for (int ks = 0; ks < 4; ks++) {
            int k = ks * 8;
            uint32_t a[4][4];
#pragma unroll
            for (int mt = 0; mt < 4; mt++) {
                int row = wm * 64 + mt * 16 + gid;
                a[mt][0] = As[row][k + tig];
                a[mt][1] = As[row + 8][k + tig];
                a[mt][2] = As[row][k + tig + 4];
                a[mt][3] = As[row + 8][k + tig + 4];
            }
#pragma unroll
            for (int nt = 0; nt < 4; nt++) {
                int n = wn * 32 + nt * 8 + gid;
                uint32_t b0 = Bs[n][k + tig];
                uint32_t b1 = Bs[n][k + tig + 4];
#pragma unroll
                for (int mt = 0; mt < 4; mt++)
                    mma1688(acc[mt][nt], a[mt][0], a[mt][1], a[mt][2], a[mt][3], b0, b1);
            }
        }
    }
#pragma unroll
    for (int mt = 0; mt < 4; mt++) {
        int rl = wm * 64 + mt * 16 + gid;
        int rA = row0 + rl, rB = rA + 8;
#pragma unroll
        for (int nt = 0; nt < 4; nt++) {
            int c0 = wn * 32 + nt * 8 + 2 * tig;
            float bb0 = 0.f, bb1 = 0.f;
            if (ga.bias) { bb0 = ga.bias[col0 + c0]; bb1 = ga.bias[col0 + c0 + 1]; }
            float v0 = acc[mt][nt][0] + bb0, v1 = acc[mt][nt][1] + bb1;
            float v2 = acc[mt][nt][2] + bb0, v3 = acc[mt][nt][3] + bb1;
            if (ga.act) {
                v0 = fmaxf(v0, 0.f); v1 = fmaxf(v1, 0.f);
                v2 = fmaxf(v2, 0.f); v3 = fmaxf(v3, 0.f);
            }
            int gc = ga.outcol + col0 + c0;
            if (rA < M) *(float2*)(ga.out + (size_t)rA * ga.outld + gc) = make_float2(v0, v1);
            if (rB < M) *(float2*)(ga.out + (size_t)rB * ga.outld + gc) = make_float2(v2, v3);
        }
    }
}

// ===================== gates =====================
__global__ void kgate(const float* __restrict__ inputs, const float* __restrict__ hidden,
                      const float* __restrict__ SR, const float* __restrict__ SI,
                      const float* __restrict__ SN,
                      const float* __restrict__ Wir, const float* __restrict__ bir,
                      const float* __restrict__ Wii, const float* __restrict__ bii,
                      const float* __restrict__ Win, const float* __restrict__ binw,
                      float* __restrict__ out) {
    const int row = blockIdx.x, col = threadIdx.x;
    __shared__ float x[6];
    if (col < 6) x[col] = inputs[row * 6 + col];
    __syncthreads();
    float xr = bir[col], xi = bii[col], xn = binw[col];
#pragma unroll
    for (int d = 0; d < 6; d++) {
        float xd = x[d];
        xr += Wir[col*6+d] * xd; xi += Wii[col*6+d] * xd; xn += Win[col*6+d] * xd;
    }
    size_t idx = (size_t)row * 256 + col;
    float rg = 1.f / (1.f + expf(-(SR[idx] + xr)));
    float ig = 1.f / (1.f + expf(-(SI[idx] + xi)));
    float ng = tanhf(xn + rg * SN[idx]);
    out[9600 + idx] = (1.f - ig) * ng + ig * hidden[idx];
}

// ===================== prediction =====================
__global__ void kpred(const float* __restrict__ inputs, const float* __restrict__ p2,
                      const float* __restrict__ Wo3, const float* __restrict__ bo3,
                      float* __restrict__ out) {
    __shared__ float sP[32 * 257];
    __shared__ float sW3[6 * 256];
    const int tid = threadIdx.x;
    const int row0 = blockIdx.x * 32;
    for (int i = tid; i < 32 * 256; i += 256) {
        int r = i >> 8, k = i & 255;
        sP[r * 257 + k] = p2[(size_t)(row0 + r) * 256 + k];
    }
    for (int i = tid; i < 1536; i += 256) sW3[i] = Wo3[i];
    __syncthreads();
    if (tid < 192) {
        int row = tid / 6, d = tid - (tid / 6) * 6;
        float s = bo3[d];
        for (int k = 0; k < 256; k++) s += sP[row * 257 + k] * sW3[d * 256 + k];
        size_t g = (size_t)(row0 + row) * 6 + d;
        out[g] = inputs[g] + s;
    }
}

// ===================== launch =====================
extern "C" void kernel_launch(void* const* d_in, const int* in_sizes, int n_in,
                              void* d_out, int out_size) {
    const float* inputs = (const float*)d_in[0];
    const float* hidden = (const float*)d_in[1];
    const float* edges  = (const float*)d_in[2];
    const float* W1     = (const float*)d_in[3];
    const float* b1     = (const float*)d_in[4];
    const float* W2     = (const float*)d_in[5];
    const float* b2     = (const float*)d_in[6];
    const float* Whr    = (const float*)d_in[7];
    const float* Whi    = (const float*)d_in[8];
    const float* Whh    = (const float*)d_in[9];
    const float* Wir    = (const float*)d_in[10];
    const float* bir    = (const float*)d_in[11];
    const float* Wii    = (const float*)d_in[12];
    const float* bii    = (const float*)d_in[13];
    const float* Win    = (const float*)d_in[14];
    const float* binw   = (const float*)d_in[15];
    const float* Wo1    = (const float*)d_in[16];
    const float* bo1    = (const float*)d_in[17];
    const float* Wo2    = (const float*)d_in[18];
    const float* bo2    = (const float*)d_in[19];
    const float* Wo3    = (const float*)d_in[20];
    const float* bo3    = (const float*)d_in[21];
    float* out = (float*)d_out;

    void* pP = nullptr; void* pAgg = nullptr;
    cudaGetSymbolAddress(&pP, g_P);
    cudaGetSymbolAddress(&pAgg, g_agg);
    float* gp = (float*)pP;
    float* gagg = (float*)pAgg;
    float* SR = gp;                 // g_P reused as scratch after k2 consumes it
    float* SI = gp + 409600;
    float* SN = gp + 819200;
    float* P1 = gp + 1228800;
    float* P2 = gp + 1638400;

    cudaFuncSetAttribute(k2_msg, cudaFuncAttributeMaxDynamicSharedMemorySize, K2_SMEM);

    // K1: node projections via mma, z -> (t, dir)
    {
        GArgs a;
        for (int z = 0; z < 6; z++) {
            int t = z >> 1, dir = z & 1;
            a.g[z].A = hidden;
            a.g[z].W = W1 + (size_t)t * 256 * 512 + dir * 256;
            a.g[z].wld = 512;
            a.g[z].bias = (dir == 0) ? (b1 + t * 256) : nullptr;
            a.g[z].out = gp;
            a.g[z].outld = 1536;
            a.g[z].outcol = (t * 2 + dir) * 256;
            a.g[z].act = 0;
        }
        kg_mma<<<dim3(13, 2, 6), 256>>>(a, NBV);
    }
    k2_msg<<<dim3(20, 32, 3), 256, K2_SMEM>>>(edges, W2, b2);
    k3_agg<<<1600, 256>>>();
    // R, I, N
    {
        GArgs a;
        const float* Ws[3] = {Whr, Whi, Whh};
        float* Os[3] = {SR, SI, SN};
        for (int z = 0; z < 3; z++) {
            a.g[z].A = gagg; a.g[z].W = Ws[z]; a.g[z].wld = 256;
            a.g[z].bias = nullptr; a.g[z].out = Os[z];
            a.g[z].outld = 256; a.g[z].outcol = 0; a.g[z].act = 0;
        }
        kg_mma<<<dim3(13, 2, 3), 256>>>(a, NBV);
    }
    kgate<<<1600, 256>>>(inputs, hidden, SR, SI, SN,
                         Wir, bir, Wii, bii, Win, binw, out);
    {
        GArgs a;
        a.g[0].A = out + 9600; a.g[0].W = Wo1; a.g[0].wld = 256;
        a.g[0].bias = bo1; a.g[0].out = P1; a.g[0].outld = 256;
        a.g[0].outcol = 0; a.g[0].act = 1;
        kg_mma<<<dim3(13, 2, 1), 256>>>(a, NBV);
        a.g[0].A = P1; a.g[0].W = Wo2; a.g[0].bias = bo2; a.g[0].out = P2;
        kg_mma<<<dim3(13, 2, 1), 256>>>(a, NBV);
    }
    kpred<<<50, 256>>>(inputs, P2, Wo3, bo3, out);
}